// round 13
// baseline (speedup 1.0000x reference)
#include <cuda_runtime.h>
#include <cuda_fp16.h>
#include <cstdint>

// final = rmsnorm( x @ (0.125 * w_out @ w_v)^T + b_out ) * g * 32
// R12 = R11 with the main GEMM made persistent (296 CTAs, 2/SM), pipeline
// carried across tile boundaries. Everything else identical to R11.

constexpr int DIM    = 1024;
constexpr int HIDDEN = 512;
constexpr int BATCH  = 16384;

constexpr int BM = 128;
constexpr int BN = 128;
constexpr int BK = 64;
constexpr int KCHUNKS  = DIM / BK;              // 16
constexpr int KCHUNKSP = HIDDEN / BK;           // 8
constexpr int NSTAGE = 3;

constexpr int NTILES = (BATCH / BM) * (DIM / BN);  // 1024
constexpr int PGRID  = 296;                        // 2 CTAs x 148 SMs

constexpr uint32_t PITCH = 144;
constexpr uint32_t SA = 0;
constexpr uint32_t SB = 128 * PITCH;
constexpr uint32_t STAGE = 2 * 128 * PITCH;     // 36864
constexpr uint32_t GEMM_SMEM = NSTAGE * STAGE;  // 110592 (also prep)

// Static device scratch (allocation-free rule).
__device__ __half g_Xh[BATCH * DIM];            // x fp16
__device__ __half g_Wh[DIM * DIM];              // W = w_out @ w_v (unscaled)
__device__ __half g_WO[DIM * HIDDEN];           // w_out fp16 [n][c]
__device__ __half g_WvT[DIM * HIDDEN];          // w_v^T fp16 [k][c]

// ---------------------------------------------------------------------------
__device__ __forceinline__ uint32_t smem_u32(const void* p) {
    uint32_t a;
    asm("{ .reg .u64 t; cvta.to.shared.u64 t, %1; cvt.u32.u64 %0, t; }"
        : "=r"(a) : "l"(p));
    return a;
}
__device__ __forceinline__ void cp16(uint32_t dst, const void* src) {
    asm volatile("cp.async.cg.shared.global [%0], [%1], 16;"
                 :: "r"(dst), "l"(src) : "memory");
}
#define CP_COMMIT() asm volatile("cp.async.commit_group;" ::: "memory")
#define CP_WAIT(n)  asm volatile("cp.async.wait_group %0;" :: "n"(n) : "memory")

#define LDSM4(r, addr)                                                         \
    asm volatile("ldmatrix.sync.aligned.m8n8.x4.shared.b16 "                   \
                 "{%0, %1, %2, %3}, [%4];"                                     \
                 : "=r"((r)[0]), "=r"((r)[1]), "=r"((r)[2]), "=r"((r)[3])      \
                 : "r"(addr))

#define MMA16816(c, a, b)                                                      \
    asm volatile("mma.sync.aligned.m16n8k16.row.col.f32.f16.f16.f32 "          \
                 "{%0, %1, %2, %3}, {%4, %5, %6, %7}, {%8, %9}, "              \
                 "{%0, %1, %2, %3};"                                           \
                 : "+f"((c)[0]), "+f"((c)[1]), "+f"((c)[2]), "+f"((c)[3])      \
                 : "r"((a)[0]), "r"((a)[1]), "r"((a)[2]), "r"((a)[3]),         \
                   "r"((b)[0]), "r"((b)[1]))

// ---------------------------------------------------------------------------
// Conversion kernel (full chip, pure memory):
//   blocks [0,2048)    : x fp32 -> fp16
//   blocks [2048,2176) : w_out -> fp16 [n][c]
//   blocks [2176,2688) : w_v -> transposed fp16 [k][c]
// ---------------------------------------------------------------------------
__global__ __launch_bounds__(256) void conv_kernel(
    const float4* __restrict__ x4,
    const float* __restrict__ w_qkv, const float* __restrict__ w_out)
{
    const int tid = threadIdx.x;
    const int b = blockIdx.x;

    if (b < 2048) {
        __half2* __restrict__ xo = reinterpret_cast<__half2*>(g_Xh);
        int i = b * 256 + tid;
        #pragma unroll
        for (int it = 0; it < 8; it++, i += 524288) {
            float4 v = x4[i];
            xo[i * 2 + 0] = __floats2half2_rn(v.x, v.y);
            xo[i * 2 + 1] = __floats2half2_rn(v.z, v.w);
        }
        return;
    }

    if (b < 2176) {
        const float4* __restrict__ w4 = reinterpret_cast<const float4*>(w_out);
        __half2* __restrict__ wo = reinterpret_cast<__half2*>(g_WO);
        int i = (b - 2048) * 256 + tid;
        #pragma unroll
        for (int it = 0; it < 4; it++, i += 32768) {
            float4 v = w4[i];
            wo[i * 2 + 0] = __floats2half2_rn(v.x, v.y);
            wo[i * 2 + 1] = __floats2half2_rn(v.z, v.w);
        }
        return;
    }

    // w_v transpose: w_v[c][k] (rows [1024,1536) of w_qkv) -> WvT[k][c]
    __shared__ float tile[32][33];
    const int bb = b - 2176;                 // 0..511
    const int k0 = (bb & 31) * 32;
    const int c0 = (bb >> 5) * 32;
    const int tx = tid & 31, ty = tid >> 5;
    const float* __restrict__ wv = w_qkv + (size_t)2 * HIDDEN * DIM;

    #pragma unroll
    for (int j = 0; j < 4; j++)
        tile[ty + j * 8][tx] = wv[(size_t)(c0 + ty + j * 8) * DIM + k0 + tx];
    __syncthreads();
    #pragma unroll
    for (int j = 0; j < 4; j++) {
        int k = k0 + ty + j * 8;
        g_WvT[(size_t)k * HIDDEN + c0 + tx] =
            __float2half_rn(tile[tx][ty + j * 8]);
    }
}

// ---------------------------------------------------------------------------
// Prep GEMM (single-pass fp16): W[n][k] = sum_c w_out[n][c] * w_vT[k][c]
// ---------------------------------------------------------------------------
__device__ __forceinline__ void load_stage_p(uint32_t sb, int s, int m0b,
                                             int n0b, int kc, int tid)
{
    const uint32_t st = sb + (uint32_t)s * STAGE;
    const char* ah = reinterpret_cast<const char*>(g_WO);
    const char* bh = reinterpret_cast<const char*>(g_WvT);
    const size_t kb = (size_t)kc * 128;

    #pragma unroll
    for (int j = 0; j < 4; j++) {
        int i = tid + j * 256;
        int r = i >> 3, c = i & 7;
        uint32_t so = (uint32_t)r * PITCH + c * 16;
        cp16(st + SA + so, ah + (size_t)(m0b + r) * 1024 + kb + c * 16);
        cp16(st + SB + so, bh + (size_t)(n0b + r) * 1024 + kb + c * 16);
    }
}

__global__ __launch_bounds__(256, 2) void prep_gemm_kernel()
{
    extern __shared__ char smem[];
    const uint32_t sb = smem_u32(smem);
    const int tid = threadIdx.x;
    const int lane = tid & 31, wid = tid >> 5;
    const int wm = wid & 1, wn = wid >> 1;
    const int m0b = blockIdx.y * BM;     // n-dim of W
    const int n0b = blockIdx.x * BN;     // k-dim of W

    float c[4][4][4] = {};

    const int rowA = lane & 15;
    const int colA = (lane >> 4) * 8;
    const int rowB = (lane & 7) + ((lane >> 4) << 3);
    const int colB = ((lane >> 3) & 1) * 8;
    const uint32_t pA = (uint32_t)(wm * 64 + rowA) * PITCH + colA * 2;
    const uint32_t pB = (uint32_t)(wn * 32 + rowB) * PITCH + colB * 2;

    load_stage_p(sb, 0, m0b, n0b, 0, tid);
    CP_COMMIT();
    load_stage_p(sb, 1, m0b, n0b, 1, tid);
    CP_COMMIT();

    int sc = 0;
    for (int kc = 0; kc < KCHUNKSP; kc++) {
        CP_WAIT(1);
        __syncthreads();

        if (kc + 2 < KCHUNKSP) {
            int sp = sc + 2; if (sp >= NSTAGE) sp -= NSTAGE;
            load_stage_p(sb, sp, m0b, n0b, kc + 2, tid);
        }
        CP_COMMIT();

        const uint32_t st = sb + (uint32_t)sc * STAGE;
        #pragma unroll
        for (int ks = 0; ks < 4; ks++) {
            uint32_t a[4][4];
            #pragma unroll
            for (int mi = 0; mi < 4; mi++)
                LDSM4(a[mi], st + SA + pA + mi * (16 * PITCH) + ks * 32);
            uint32_t b[4][2];
            #pragma unroll
            for (int np = 0; np < 2; np++) {
                uint32_t r[4];
                LDSM4(r, st + SB + pB + np * (16 * PITCH) + ks * 32);
                b[np * 2][0] = r[0]; b[np * 2][1] = r[1];
                b[np * 2 + 1][0] = r[2]; b[np * 2 + 1][1] = r[3];
            }
            #pragma unroll
            for (int mi = 0; mi < 4; mi++)
                #pragma unroll
                for (int ni = 0; ni < 4; ni++)
                    MMA16816(c[mi][ni], a[mi], b[ni]);
        }
        if (++sc >= NSTAGE) sc -= NSTAGE;
    }

    const int mbase = m0b + wm * 64 + (lane >> 2);
    const int nbase = n0b + wn * 32 + (lane & 3) * 2;
    #pragma unroll
    for (int ni = 0; ni < 4; ni++) {
        const int n = nbase + ni * 8;
        #pragma unroll
        for (int mi = 0; mi < 4; mi++) {
            const int m = mbase + mi * 16;
            *reinterpret_cast<__half2*>(&g_Wh[(size_t)m * DIM + n]) =
                __floats2half2_rn(c[mi][ni][0], c[mi][ni][1]);
            *reinterpret_cast<__half2*>(&g_Wh[(size_t)(m + 8) * DIM + n]) =
                __floats2half2_rn(c[mi][ni][2], c[mi][ni][3]);
        }
    }
}

// ---------------------------------------------------------------------------
// Main GEMM (persistent): out[b][n] = 0.125*sum_k X[b][k]*W[n][k] + b_out[n]
// 296 CTAs; each loops tiles t = bid, bid+296, ...; cp.async pipeline is
// carried across tile boundaries (prefetch of next tile's chunks 0/1 happens
// during this tile's last two chunks; epilogue overlaps those loads).
// ---------------------------------------------------------------------------
__device__ __forceinline__ void load_stage(uint32_t sb, int s, int m0b, int n0b,
                                           int kc, int tid)
{
    const uint32_t st = sb + (uint32_t)s * STAGE;
    const char* xh = reinterpret_cast<const char*>(g_Xh);
    const char* wh = reinterpret_cast<const char*>(g_Wh);
    const size_t kb = (size_t)kc * 128;

    #pragma unroll
    for (int j = 0; j < 4; j++) {
        int i = tid + j * 256;
        int r = i >> 3, c = i & 7;
        uint32_t so = (uint32_t)r * PITCH + c * 16;
        cp16(st + SA + so, xh + (size_t)(m0b + r) * 2048 + kb + c * 16);
        cp16(st + SB + so, wh + (size_t)(n0b + r) * 2048 + kb + c * 16);
    }
}

__device__ __forceinline__ int tile_m(int t) { return (t >> 3) * BM; }
__device__ __forceinline__ int tile_n(int t) { return (t & 7) * BN; }

__global__ __launch_bounds__(256, 2) void gemm_mma_kernel(
    const float* __restrict__ b_out, float* __restrict__ out)
{
    extern __shared__ char smem[];
    const uint32_t sb = smem_u32(smem);
    const int tid = threadIdx.x;
    const int lane = tid & 31, wid = tid >> 5;
    const int wm = wid & 1, wn = wid >> 1;
    const int bid = blockIdx.x;

    const int rowA = lane & 15;
    const int colA = (lane >> 4) * 8;
    const int rowB = (lane & 7) + ((lane >> 4) << 3);
    const int colB = ((lane >> 3) & 1) * 8;
    const uint32_t pA = (uint32_t)(wm * 64 + rowA) * PITCH + colA * 2;
    const uint32_t pB = (uint32_t)(wn * 32 + rowB) * PITCH + colB * 2;

    // prologue: first tile's chunks 0 and 1
    load_stage(sb, 0, tile_m(bid), tile_n(bid), 0, tid);
    CP_COMMIT();
    load_stage(sb, 1, tile_m(bid), tile_n(bid), 1, tid);
    CP_COMMIT();

    int sc = 0;
    for (int t = bid; t < NTILES; t += PGRID) {
        const int m0b = tile_m(t), n0b = tile_n(t);
        float c[4][4][4] = {};

        for (int kc = 0; kc < KCHUNKS; kc++) {
            CP_WAIT(1);
            __syncthreads();

            // prefetch global chunk +2 (this tile or next tile's chunk 0/1)
            {
                const int pk = kc + 2;
                int sp = sc + 2; if (sp >= NSTAGE) sp -= NSTAGE;
                if (pk < KCHUNKS) {
                    load_stage(sb, sp, m0b, n0b, pk, tid);
                } else if (t + PGRID < NTILES) {
                    load_stage(sb, sp, tile_m(t + PGRID), tile_n(t + PGRID),
                               pk - KCHUNKS, tid);
                }
            }
            CP_COMMIT();

            const uint32_t st = sb + (uint32_t)sc * STAGE;
            #pragma unroll
            for (int ks = 0; ks < 4; ks++) {
                uint32_t a[4][4];
                #pragma unroll
                for (int mi = 0; mi < 4; mi++)
                    LDSM4(a[mi], st + SA + pA + mi * (16 * PITCH) + ks * 32);
                uint32_t b[4][2];
                #pragma unroll
                for (int np = 0; np < 2; np++) {
                    uint32_t r[4];
                    LDSM4(r, st + SB + pB + np * (16 * PITCH) + ks * 32);
                    b[np * 2][0] = r[0]; b[np * 2][1] = r[1];
                    b[np * 2 + 1][0] = r[2]; b[np * 2 + 1][1] = r[3];
                }
                #pragma unroll
                for (int mi = 0; mi < 4; mi++)
                    #pragma unroll
                    for (int ni = 0; ni < 4; ni++)
                        MMA16816(c[mi][ni], a[mi], b[ni]);
            }
            if (++sc >= NSTAGE) sc -= NSTAGE;
        }

        // epilogue for tile t (overlaps next tile's in-flight cp.asyncs)
        const int mbase = m0b + wm * 64 + (lane >> 2);
        const int nbase = n0b + wn * 32 + (lane & 3) * 2;
        #pragma unroll
        for (int ni = 0; ni < 4; ni++) {
            const int n = nbase + ni * 8;
            const float2 bias = *reinterpret_cast<const float2*>(&b_out[n]);
            #pragma unroll
            for (int mi = 0; mi < 4; mi++) {
                const int m = mbase + mi * 16;
                float2 v0 = { fmaf(0.125f, c[mi][ni][0], bias.x),
                              fmaf(0.125f, c[mi][ni][1], bias.y) };
                float2 v1 = { fmaf(0.125f, c[mi][ni][2], bias.x),
                              fmaf(0.125f, c[mi][ni][3], bias.y) };
                *reinterpret_cast<float2*>(&out[(size_t)m * DIM + n]) = v0;
                *reinterpret_cast<float2*>(&out[(size_t)(m + 8) * DIM + n]) = v1;
            }
        }
    }
}

// ---------------------------------------------------------------------------
// Row L2-normalize: out = y * (32/max(||y||,eps)) * g
// ---------------------------------------------------------------------------
__global__ __launch_bounds__(256) void rmsnorm_kernel(
    const float* __restrict__ g, float* __restrict__ y)
{
    const int warp = (blockIdx.x * blockDim.x + threadIdx.x) >> 5;
    const int lane = threadIdx.x & 31;
    if (warp >= BATCH) return;
    float* __restrict__ row = y + (size_t)warp * DIM;

    float4 vals[8];
    float ss = 0.f;
    #pragma unroll
    for (int i = 0; i < 8; i++) {
        vals[i] = *reinterpret_cast<const float4*>(&row[lane * 4 + i * 128]);
        ss += vals[i].x * vals[i].x + vals[i].y * vals[i].y +
              vals[i].z * vals[i].z + vals[i].w * vals[i].w;
    }
    #pragma unroll
    for (int o = 16; o > 0; o >>= 1) ss += __shfl_xor_sync(0xFFFFFFFFu, ss, o);
    const float inv = 32.0f / fmaxf(sqrtf(ss), 1e-12f);
    #pragma unroll
    for (int i = 0; i < 8; i++) {
        int n = lane * 4 + i * 128;
        float4 gv = *reinterpret_cast<const float4*>(&g[n]);
        float4 o;
        o.x = vals[i].x * inv * gv.x;
        o.y = vals[i].y * inv * gv.y;
        o.z = vals[i].z * inv * gv.z;
        o.w = vals[i].w * inv * gv.w;
        *reinterpret_cast<float4*>(&row[n]) = o;
    }
}

// ---------------------------------------------------------------------------
extern "C" void kernel_launch(void* const* d_in, const int* in_sizes, int n_in,
                              void* d_out, int out_size)
{
    const float* x     = (const float*)d_in[0];
    const float* w_qkv = (const float*)d_in[1];
    const float* w_out = (const float*)d_in[2];
    const float* b_out = (const float*)d_in[3];
    const float* g     = (const float*)d_in[4];
    float* out = (float*)d_out;

    cudaFuncSetAttribute(gemm_mma_kernel,
                         cudaFuncAttributeMaxDynamicSharedMemorySize, GEMM_SMEM);
    cudaFuncSetAttribute(prep_gemm_kernel,
                         cudaFuncAttributeMaxDynamicSharedMemorySize, GEMM_SMEM);

    conv_kernel<<<2688, 256>>>((const float4*)x, w_qkv, w_out);
    prep_gemm_kernel<<<dim3(DIM / BN, DIM / BM), 256, GEMM_SMEM>>>();
    gemm_mma_kernel<<<PGRID, 256, GEMM_SMEM>>>(b_out, out);
    rmsnorm_kernel<<<(BATCH * 32) / 256, 256>>>(g, out);
}